// round 5
// baseline (speedup 1.0000x reference)
#include <cuda_runtime.h>
#include <cstdint>

// ============================ problem constants ============================
#define SS 2048
#define DD 4096
#define VV 32000
#define MROWS 4094          // B*(S-1)
#define MPAD  4096          // padded GEMM M

// scratch (device globals — allocation-free rule)
// A in mma-fragment-permuted layout: [m16_block(256)][kstep(512)][lane(32)][4 floats]
__device__ float g_act[(size_t)MPAD * DD];
// B in mma-fragment-permuted layout: [n8_block(4000)][kstep(512)][lane(32)][2 floats]
__device__ float g_w[(size_t)VV * DD];

// ============================ helpers ============================
__device__ __forceinline__ uint32_t smem_u32(const void* p) {
    uint32_t a;
    asm("{ .reg .u64 t; cvta.to.shared.u64 t, %1; cvt.u32.u64 %0, t; }" : "=r"(a) : "l"(p));
    return a;
}
__device__ __forceinline__ void cp16(uint32_t dst, const void* src) {
    asm volatile("cp.async.cg.shared.global [%0], [%1], 16;" :: "r"(dst), "l"(src));
}
#define CP_COMMIT() asm volatile("cp.async.commit_group;" ::: "memory")
#define CP_WAIT2()  asm volatile("cp.async.wait_group 2;" ::: "memory")

__device__ __forceinline__ void mma_tf32(float* d, const uint32_t* a, const uint32_t* b) {
    asm volatile(
        "mma.sync.aligned.m16n8k8.row.col.f32.tf32.tf32.f32 "
        "{%0,%1,%2,%3}, {%4,%5,%6,%7}, {%8,%9}, {%0,%1,%2,%3};"
        : "+f"(d[0]), "+f"(d[1]), "+f"(d[2]), "+f"(d[3])
        : "r"(a[0]), "r"(a[1]), "r"(a[2]), "r"(a[3]), "r"(b[0]), "r"(b[1]));
}

__device__ __forceinline__ float rtf32(float f) {  // round-to-nearest tf32
    uint32_t u = __float_as_uint(f);
    u = (u + 0x1000u) & 0xFFFFE000u;
    return __uint_as_float(u);
}

// ============================ prolog kernels ============================
// Permute + tf32-round lm_head_weight [VV, DD] row-major -> g_w fragment layout.
// Fragment layout for mma.m16n8k8 B (k x n, col-major): for n8 block, kstep:
//   lane = (n%8)*4 + (k%4);  reg0 = k (k%8<4), reg1 = k+4.  slot = float2.
__global__ void __launch_bounds__(256) wperm_kernel(const float* __restrict__ w,
                                                    float* __restrict__ o) {
    int gid = blockIdx.x * 256 + threadIdx.x;     // 32000*512 threads
    int n  = gid >> 9;
    int kg = gid & 511;                            // k-group of 8
    const float4* src = reinterpret_cast<const float4*>(w + (size_t)n * DD + kg * 8);
    float4 v0 = src[0], v1 = src[1];
    float a0 = rtf32(v0.x), a1 = rtf32(v0.y), a2 = rtf32(v0.z), a3 = rtf32(v0.w);
    float a4 = rtf32(v1.x), a5 = rtf32(v1.y), a6 = rtf32(v1.z), a7 = rtf32(v1.w);
    size_t base = ((size_t)(n >> 3) * 512 + kg) * 32 + (n & 7) * 4;  // float2 index
    float2* dst = reinterpret_cast<float2*>(o) + base;
    dst[0] = make_float2(a0, a4);
    dst[1] = make_float2(a1, a5);
    dst[2] = make_float2(a2, a6);
    dst[3] = make_float2(a3, a7);
}

// RMSNorm one (shifted) row per block, tf32-rounded, written in A fragment layout.
// Fragment layout for mma.m16n8k8 A (m x k, row-major): within m16 block, kstep:
//   lane = (ri%8)*4 + (k%4);  reg = (ri/8) + 2*((k%8)/4).
__global__ void __launch_bounds__(256) rmsperm_kernel(const float* __restrict__ x,
                                                      const float* __restrict__ w,
                                                      float* __restrict__ o) {
    __shared__ float red[8];
    int r = blockIdx.x, t = threadIdx.x;
    float vals[16];
    if (r < MROWS) {
        int b = r / (SS - 1);
        int s = r - b * (SS - 1);
        const float4* xr = reinterpret_cast<const float4*>(x + ((size_t)b * SS + s) * DD + t * 16);
        const float4* wr = reinterpret_cast<const float4*>(w + t * 16);
        float4 q[4];
        float acc = 0.f;
#pragma unroll
        for (int i = 0; i < 4; ++i) {
            q[i] = xr[i];
            acc += q[i].x * q[i].x + q[i].y * q[i].y + q[i].z * q[i].z + q[i].w * q[i].w;
        }
#pragma unroll
        for (int off = 16; off; off >>= 1) acc += __shfl_xor_sync(0xffffffffu, acc, off);
        if ((t & 31) == 0) red[t >> 5] = acc;
        __syncthreads();
        float tot = red[0] + red[1] + red[2] + red[3] + red[4] + red[5] + red[6] + red[7];
        float rs = rsqrtf(tot * (1.0f / DD) + 1e-6f);
#pragma unroll
        for (int i = 0; i < 4; ++i) {
            float4 wv = wr[i];
            vals[4 * i + 0] = rtf32(q[i].x * rs * wv.x);
            vals[4 * i + 1] = rtf32(q[i].y * rs * wv.y);
            vals[4 * i + 2] = rtf32(q[i].z * rs * wv.z);
            vals[4 * i + 3] = rtf32(q[i].w * rs * wv.w);
        }
    } else {
#pragma unroll
        for (int i = 0; i < 16; ++i) vals[i] = 0.f;
        __syncthreads();   // keep barrier count uniform (blocks < MROWS hit one)
    }
    int m16 = r >> 4, ri = r & 15;
    int laneb = (ri & 7) * 4;
    int r0 = ri >> 3;
#pragma unroll
    for (int g = 0; g < 2; ++g) {                       // kstep = t*2 + g
        size_t slot = ((size_t)m16 * 512 + t * 2 + g) * 32;
#pragma unroll
        for (int c = 0; c < 4; ++c) {
            size_t fo = (slot + laneb + c) * 4;
            o[fo + r0]     = vals[g * 8 + c];           // a0/a1 (k = c)
            o[fo + r0 + 2] = vals[g * 8 + c + 4];       // a2/a3 (k = c+4)
        }
    }
}

// Shifted labels into tail of d_out.
// Device labels are INT32 (proven R3: int64-read gave 2^32-scale garbage).
// Output tail is FLOAT32 (proven R4: int-bit writes read back as denormals -> rel_err 1.0),
// so store the label VALUE converted to float (labels < 2^24, exact).
__global__ void __launch_bounds__(256) labels_kernel(const int* __restrict__ lab,
                                                     float* __restrict__ out, long long rem) {
    int i = blockIdx.x * blockDim.x + threadIdx.x;
    if (i >= MROWS) return;
    int b = i / (SS - 1);
    int s = i - b * (SS - 1);
    int v = lab[(size_t)b * SS + s + 1];
    size_t base = (size_t)MROWS * VV;
    if (rem >= 2LL * MROWS) {
        // improbable layout (int64 tail): write widened value
        reinterpret_cast<long long*>(out + base)[i] = (long long)v;
    } else if (rem >= (long long)MROWS) {
        out[base + i] = (float)v;   // float32 tail (the actual layout)
    }
}

// ============================ GEMM kernel ============================
// CTA tile 128(M) x 128(N), kBlock 32, 3-stage cp.async pipeline, 256 threads.
// Warps 4(m) x 2(n); warp tile 32 x 64; per-thread 2x8 mma accum tiles (64 regs).
#define NSTG      3
#define STG_BYTES 32768                 // A 16KB + B 16KB per stage
#define KBLOCKS   (DD / 32)             // 128

__global__ void __launch_bounds__(256, 2) gemm_kernel(const float* __restrict__ A,
                                                      const float* __restrict__ B,
                                                      float* __restrict__ out) {
    extern __shared__ char smem[];
    uint32_t sbase = smem_u32(smem);
    int t = threadIdx.x;
    int lane = t & 31, wid = t >> 5;
    int wm = wid & 3, wn = wid >> 2;
    int m_tile = blockIdx.x & 31;       // m fastest: A stays L2-resident
    int n_tile = blockIdx.x >> 5;

    const char* Ab = (const char*)A;
    const char* Bb = (const char*)B;

    // ---- stage fill: pure 16B cp.async copies (layouts identical gmem<->smem)
    int aw = t >> 5, al = t & 31;       // A: piece = pp*8 + aw
    auto load_stage = [&](int st, int kb) {
        uint32_t dstA = sbase + st * STG_BYTES;
        uint32_t dstB = dstA + 16384;
#pragma unroll
        for (int pp = 0; pp < 4; ++pp) {
            int p = pp * 8 + aw;                       // p = m16b*4 + ks
            int m16b = p >> 2, ks = p & 3;
            const char* src = Ab + (((((size_t)(m_tile * 8 + m16b)) * 512 + kb * 4 + ks) * 32 + al) << 4);
            cp16(dstA + ((p * 32 + al) << 4), src);
        }
#pragma unroll
        for (int pp = 0; pp < 4; ++pp) {
            int q = pp * 256 + t;                      // 16B chunk id in B stage
            int piece = q >> 4, within = q & 15;       // piece = n8b*4 + ks (256B)
            int n8b = piece >> 2, ks = piece & 3;
            const char* src = Bb + (((((size_t)(n_tile * 16 + n8b)) * 512 + kb * 4 + ks) * 32) << 3)
                                 + (within << 4);
            cp16(dstB + (q << 4), src);
        }
    };

    float acc[2][8][4];
#pragma unroll
    for (int i = 0; i < 2; ++i)
#pragma unroll
        for (int j = 0; j < 8; ++j)
#pragma unroll
            for (int c = 0; c < 4; ++c) acc[i][j][c] = 0.f;

    // prologue: fill 3 stages
#pragma unroll
    for (int s = 0; s < NSTG; ++s) {
        load_stage(s, s);
        CP_COMMIT();
    }

    int st = 0;
    for (int kb = 0; kb < KBLOCKS; ++kb) {
        CP_WAIT2();
        __syncthreads();
        const uint4* Asp = reinterpret_cast<const uint4*>(smem + st * STG_BYTES);
        const uint2* Bsp = reinterpret_cast<const uint2*>(smem + st * STG_BYTES + 16384);
#pragma unroll
        for (int ks = 0; ks < 4; ++ks) {
            uint4 a[2];
            uint2 b[8];
#pragma unroll
            for (int i = 0; i < 2; ++i)
                a[i] = Asp[(((wm * 2 + i) * 4 + ks) * 32) + lane];
#pragma unroll
            for (int j = 0; j < 8; ++j)
                b[j] = Bsp[(((wn * 8 + j) * 4 + ks) * 32) + lane];
#pragma unroll
            for (int i = 0; i < 2; ++i)
#pragma unroll
                for (int j = 0; j < 8; ++j)
                    mma_tf32(acc[i][j], (const uint32_t*)&a[i], (const uint32_t*)&b[j]);
        }
        __syncthreads();
        if (kb + NSTG < KBLOCKS) load_stage(st, kb + NSTG);
        CP_COMMIT();
        st = (st == NSTG - 1) ? 0 : st + 1;
    }

    // ---- epilogue: fragment layout -> row-major fp32 logits
    int gq = lane >> 2, tq = lane & 3;
#pragma unroll
    for (int i = 0; i < 2; ++i) {
        int r0 = m_tile * 128 + wm * 32 + i * 16 + gq;
#pragma unroll
        for (int j = 0; j < 8; ++j) {
            int col = n_tile * 128 + wn * 64 + j * 8 + tq * 2;
            if (r0 < MROWS)
                *reinterpret_cast<float2*>(out + (size_t)r0 * VV + col) =
                    make_float2(acc[i][j][0], acc[i][j][1]);
            if (r0 + 8 < MROWS)
                *reinterpret_cast<float2*>(out + (size_t)(r0 + 8) * VV + col) =
                    make_float2(acc[i][j][2], acc[i][j][3]);
        }
    }
}

// ============================ host launcher ============================
extern "C" void kernel_launch(void* const* d_in, const int* in_sizes, int n_in,
                              void* d_out, int out_size) {
    const float* hs  = (const float*)d_in[0];
    const float* nw  = (const float*)d_in[1];
    const float* lmw = (const float*)d_in[2];
    const int*   lab = (const int*)d_in[4];
    float* out = (float*)d_out;

    void* act_ptr = nullptr; cudaGetSymbolAddress(&act_ptr, g_act);
    void* w_ptr   = nullptr; cudaGetSymbolAddress(&w_ptr, g_w);

    // prolog: permute/round weights + rmsnorm activations + labels
    wperm_kernel<<<(VV * 512) / 256, 256>>>(lmw, (float*)w_ptr);
    rmsperm_kernel<<<MPAD, 256>>>(hs, nw, (float*)act_ptr);
    long long rem = (long long)out_size - (long long)MROWS * VV;
    labels_kernel<<<(MROWS + 255) / 256, 256>>>(lab, out, rem);

    // GEMM: 32 m-tiles x 250 n-tiles
    cudaFuncSetAttribute(gemm_kernel, cudaFuncAttributeMaxDynamicSharedMemorySize,
                         NSTG * STG_BYTES);
    gemm_kernel<<<32 * 250, 256, NSTG * STG_BYTES>>>((const float*)act_ptr,
                                                     (const float*)w_ptr, out);
}

// round 6
// speedup vs baseline: 1.9050x; 1.9050x over previous
#include <cuda_runtime.h>
#include <cuda_fp16.h>
#include <cstdint>

// ============================ problem constants ============================
#define SS 2048
#define DD 4096
#define VV 32000
#define MROWS 4094          // B*(S-1)
#define MPAD  4096          // padded GEMM M

// scratch (device globals — allocation-free rule), fp16 operands
// A fragment layout (mma.m16n8k16 A): [m16_blk(256)][k16_step(256)][lane(32)][a0,a1,a2,a3 half2] (16B/lane)
__device__ __half g_act[(size_t)MPAD * DD];
// B fragment layout (mma.m16n8k16 B): [n8_blk(4000)][k16_step(256)][lane(32)][b0,b1 half2] (8B/lane)
__device__ __half g_w[(size_t)VV * DD];

// ============================ helpers ============================
__device__ __forceinline__ uint32_t smem_u32(const void* p) {
    uint32_t a;
    asm("{ .reg .u64 t; cvta.to.shared.u64 t, %1; cvt.u32.u64 %0, t; }" : "=r"(a) : "l"(p));
    return a;
}
__device__ __forceinline__ void cp16(uint32_t dst, const void* src) {
    asm volatile("cp.async.cg.shared.global [%0], [%1], 16;" :: "r"(dst), "l"(src));
}
#define CP_COMMIT() asm volatile("cp.async.commit_group;" ::: "memory")
#define CP_WAIT2()  asm volatile("cp.async.wait_group 2;" ::: "memory")

__device__ __forceinline__ void mma_f16(float* d, const uint32_t* a, const uint32_t* b) {
    asm volatile(
        "mma.sync.aligned.m16n8k16.row.col.f32.f16.f16.f32 "
        "{%0,%1,%2,%3}, {%4,%5,%6,%7}, {%8,%9}, {%0,%1,%2,%3};"
        : "+f"(d[0]), "+f"(d[1]), "+f"(d[2]), "+f"(d[3])
        : "r"(a[0]), "r"(a[1]), "r"(a[2]), "r"(a[3]), "r"(b[0]), "r"(b[1]));
}

__device__ __forceinline__ uint32_t packh2(float lo, float hi) {
    __half2 h = __floats2half2_rn(lo, hi);
    return *reinterpret_cast<uint32_t*>(&h);
}

// ============================ prolog kernels ============================
// Permute + fp16-round lm_head_weight [VV, DD] -> g_w fragment layout.
// One thread per (n, k16-group): reads 16 floats, writes 32B contiguous
// (4 lanes x {b0,b1}); lane = (n%8)*4 + (k>>1)%4, b0:k<8, b1:k>=8.
__global__ void __launch_bounds__(256) wperm_kernel(const float* __restrict__ w,
                                                    uint32_t* __restrict__ o) {
    int gid = blockIdx.x * 256 + threadIdx.x;      // VV * 256 threads
    int n  = gid >> 8;
    int kg = gid & 255;                            // k16 step
    const float4* src = reinterpret_cast<const float4*>(w + (size_t)n * DD + kg * 16);
    float4 v0 = src[0], v1 = src[1], v2 = src[2], v3 = src[3];
    float h[16] = { v0.x, v0.y, v0.z, v0.w, v1.x, v1.y, v1.z, v1.w,
                    v2.x, v2.y, v2.z, v2.w, v3.x, v3.y, v3.z, v3.w };
    // dst: (((n>>3)*256 + kg)*32 + (n&7)*4) lanes, 2 uint32 per lane
    size_t laneBase = (((size_t)(n >> 3) * 256 + kg) * 32 + (n & 7) * 4);
    uint4* dst = reinterpret_cast<uint4*>(o + laneBase * 2);
    uint4 q0, q1;
    q0.x = packh2(h[0], h[1]);  q0.y = packh2(h[8],  h[9]);    // lane c=0: b0,b1
    q0.z = packh2(h[2], h[3]);  q0.w = packh2(h[10], h[11]);   // lane c=1
    q1.x = packh2(h[4], h[5]);  q1.y = packh2(h[12], h[13]);   // lane c=2
    q1.z = packh2(h[6], h[7]);  q1.w = packh2(h[14], h[15]);   // lane c=3
    dst[0] = q0;
    dst[1] = q1;
}

// RMSNorm one (shifted) row per block, fp16-rounded, A fragment layout.
// Thread t handles k16 step s=t of its row.
__global__ void __launch_bounds__(256) rmsperm_kernel(const float* __restrict__ x,
                                                      const float* __restrict__ w,
                                                      uint32_t* __restrict__ o) {
    __shared__ float red[8];
    int r = blockIdx.x, t = threadIdx.x;
    float vals[16];
    if (r < MROWS) {
        int b = r / (SS - 1);
        int s = r - b * (SS - 1);
        const float4* xr = reinterpret_cast<const float4*>(x + ((size_t)b * SS + s) * DD + t * 16);
        const float4* wr = reinterpret_cast<const float4*>(w + t * 16);
        float4 q[4];
        float acc = 0.f;
#pragma unroll
        for (int i = 0; i < 4; ++i) {
            q[i] = xr[i];
            acc += q[i].x * q[i].x + q[i].y * q[i].y + q[i].z * q[i].z + q[i].w * q[i].w;
        }
#pragma unroll
        for (int off = 16; off; off >>= 1) acc += __shfl_xor_sync(0xffffffffu, acc, off);
        if ((t & 31) == 0) red[t >> 5] = acc;
        __syncthreads();
        float tot = red[0] + red[1] + red[2] + red[3] + red[4] + red[5] + red[6] + red[7];
        float rs = rsqrtf(tot * (1.0f / DD) + 1e-6f);
#pragma unroll
        for (int i = 0; i < 4; ++i) {
            float4 wv = wr[i];
            vals[4 * i + 0] = q[i].x * rs * wv.x;
            vals[4 * i + 1] = q[i].y * rs * wv.y;
            vals[4 * i + 2] = q[i].z * rs * wv.z;
            vals[4 * i + 3] = q[i].w * rs * wv.w;
        }
    } else {
#pragma unroll
        for (int i = 0; i < 16; ++i) vals[i] = 0.f;
        __syncthreads();   // keep barrier count uniform
    }
    int m16 = r >> 4, ri = r & 15;
    int slotb = ri >> 3;                       // a0/a2 rows 0-7, a1/a3 rows 8-15
    size_t laneBase = ((size_t)m16 * 256 + t) * 32 + (ri & 7) * 4;
#pragma unroll
    for (int c = 0; c < 4; ++c) {
        size_t li = (laneBase + c) * 4;        // 4 uint32 per lane
        o[li + slotb]     = packh2(vals[2 * c],     vals[2 * c + 1]);   // k<8
        o[li + slotb + 2] = packh2(vals[2 * c + 8], vals[2 * c + 9]);   // k>=8
    }
}

// Shifted labels -> float32 tail of d_out (layout proven in R3/R4).
__global__ void __launch_bounds__(256) labels_kernel(const int* __restrict__ lab,
                                                     float* __restrict__ out, long long rem) {
    int i = blockIdx.x * blockDim.x + threadIdx.x;
    if (i >= MROWS) return;
    int b = i / (SS - 1);
    int s = i - b * (SS - 1);
    int v = lab[(size_t)b * SS + s + 1];
    size_t base = (size_t)MROWS * VV;
    if (rem >= 2LL * MROWS) {
        reinterpret_cast<long long*>(out + base)[i] = (long long)v;
    } else if (rem >= (long long)MROWS) {
        out[base + i] = (float)v;
    }
}

// ============================ GEMM kernel ============================
// CTA tile 128(M) x 128(N), kBlock 64 (4 k16 steps), 3-stage cp.async pipeline,
// 256 threads = 8 warps (4m x 2n); warp tile 32x64; 64 fp32 accums/thread.
#define NSTG      3
#define STG_BYTES 32768                 // A 16KB + B 16KB per stage
#define KBLOCKS   (DD / 64)             // 64

__global__ void __launch_bounds__(256, 2) gemm_kernel(const __half* __restrict__ A,
                                                      const __half* __restrict__ B,
                                                      float* __restrict__ out) {
    extern __shared__ char smem[];
    uint32_t sbase = smem_u32(smem);
    int t = threadIdx.x;
    int lane = t & 31, wid = t >> 5;
    int wm = wid & 3, wn = wid >> 2;
    int m_tile = blockIdx.x & 31;       // m fastest: A (32MB fp16) stays L2-resident
    int n_tile = blockIdx.x >> 5;

    const char* Ab = (const char*)A;
    const char* Bb = (const char*)B;

    // stage fill: pure 16B cp.async copies (gmem fragment layout == smem layout)
    auto load_stage = [&](int st, int kb) {
        uint32_t dstA = sbase + st * STG_BYTES;
        uint32_t dstB = dstA + 16384;
#pragma unroll
        for (int pp = 0; pp < 4; ++pp) {            // A: 1024 x 16B chunks
            int q = pp * 256 + t;
            int ln = q & 31, ks = (q >> 5) & 3, m16b = q >> 7;
            const char* src = Ab + ((((size_t)(m_tile * 8 + m16b) * 256 + kb * 4 + ks) * 32 + ln) << 4);
            cp16(dstA + (q << 4), src);
        }
#pragma unroll
        for (int pp = 0; pp < 4; ++pp) {            // B: 1024 x 16B chunks (2 lanes each)
            int q = pp * 256 + t;
            int ln2 = q & 15, ks = (q >> 4) & 3, n8b = q >> 6;
            const char* src = Bb + ((((size_t)(n_tile * 16 + n8b) * 256 + kb * 4 + ks) * 32 + ln2 * 2) << 3);
            cp16(dstB + (q << 4), src);
        }
    };

    float acc[2][8][4];
#pragma unroll
    for (int i = 0; i < 2; ++i)
#pragma unroll
        for (int j = 0; j < 8; ++j)
#pragma unroll
            for (int c = 0; c < 4; ++c) acc[i][j][c] = 0.f;

#pragma unroll
    for (int s = 0; s < NSTG; ++s) {
        load_stage(s, s);
        CP_COMMIT();
    }

    int st = 0;
    for (int kb = 0; kb < KBLOCKS; ++kb) {
        CP_WAIT2();
        __syncthreads();
        const uint4* Asp = reinterpret_cast<const uint4*>(smem + st * STG_BYTES);
        const uint2* Bsp = reinterpret_cast<const uint2*>(smem + st * STG_BYTES + 16384);
#pragma unroll
        for (int ks = 0; ks < 4; ++ks) {
            uint4 a[2];
            uint2 b[8];
#pragma unroll
            for (int i = 0; i < 2; ++i)
                a[i] = Asp[(((wm * 2 + i) * 4 + ks) * 32) + lane];
#pragma unroll
            for (int j = 0; j < 8; ++j)
                b[j] = Bsp[(((wn * 8 + j) * 4 + ks) * 32) + lane];
#pragma unroll
            for (int i = 0; i < 2; ++i)
#pragma unroll
                for (int j = 0; j < 8; ++j)
                    mma_f16(acc[i][j], (const uint32_t*)&a[i], (const uint32_t*)&b[j]);
        }
        __syncthreads();
        if (kb + NSTG < KBLOCKS) load_stage(st, kb + NSTG);
        CP_COMMIT();
        st = (st == NSTG - 1) ? 0 : st + 1;
    }

    // epilogue: fragment layout -> row-major fp32 logits
    int gq = lane >> 2, tq = lane & 3;
#pragma unroll
    for (int i = 0; i < 2; ++i) {
        int r0 = m_tile * 128 + wm * 32 + i * 16 + gq;
#pragma unroll
        for (int j = 0; j < 8; ++j) {
            int col = n_tile * 128 + wn * 64 + j * 8 + tq * 2;
            if (r0 < MROWS)
                *reinterpret_cast<float2*>(out + (size_t)r0 * VV + col) =
                    make_float2(acc[i][j][0], acc[i][j][1]);
            if (r0 + 8 < MROWS)
                *reinterpret_cast<float2*>(out + (size_t)(r0 + 8) * VV + col) =
                    make_float2(acc[i][j][2], acc[i][j][3]);
        }
    }
}

// ============================ host launcher ============================
extern "C" void kernel_launch(void* const* d_in, const int* in_sizes, int n_in,
                              void* d_out, int out_size) {
    const float* hs  = (const float*)d_in[0];
    const float* nw  = (const float*)d_in[1];
    const float* lmw = (const float*)d_in[2];
    const int*   lab = (const int*)d_in[4];
    float* out = (float*)d_out;

    void* act_ptr = nullptr; cudaGetSymbolAddress(&act_ptr, g_act);
    void* w_ptr   = nullptr; cudaGetSymbolAddress(&w_ptr, g_w);

    // prolog: permute/round weights + rmsnorm activations + labels
    wperm_kernel<<<VV, 256>>>(lmw, (uint32_t*)w_ptr);
    rmsperm_kernel<<<MPAD, 256>>>(hs, nw, (uint32_t*)act_ptr);
    long long rem = (long long)out_size - (long long)MROWS * VV;
    labels_kernel<<<(MROWS + 255) / 256, 256>>>(lab, out, rem);

    // GEMM: 32 m-tiles x 250 n-tiles
    cudaFuncSetAttribute(gemm_kernel, cudaFuncAttributeMaxDynamicSharedMemorySize,
                         NSTG * STG_BYTES);
    gemm_kernel<<<32 * 250, 256, NSTG * STG_BYTES>>>((const __half*)act_ptr,
                                                     (const __half*)w_ptr, out);
}